// round 16
// baseline (speedup 1.0000x reference)
#include <cuda_runtime.h>
#include <math.h>

// ---------------------------------------------------------------------------
// DepthModule: plane-sweep stereo depth network, fp32 with packed f32x2 FMA.
// R16: conv3d_main -> 240-thr blocks, 2/SM (15 warps/SM, 1.08 waves);
//      conv2s -> ic-split x2 + combine; logits -> ic-split x2, bias dropped
//      (softmax shift-invariance), partials summed in depth_out.
// ---------------------------------------------------------------------------

#define N_F1 (5*32*240*320)
#define N_F2 (5*32*120*160)
#define N_F3 (5*32*60*80)
#define N_VOX (32*60*80)          // 153600

typedef unsigned long long u64;

__device__ __forceinline__ u64 pk(float lo, float hi) {
    u64 r; asm("mov.b64 %0, {%1, %2};" : "=l"(r) : "f"(lo), "f"(hi)); return r;
}
__device__ __forceinline__ u64 pk2(float v) { return pk(v, v); }
__device__ __forceinline__ u64 f2fma(u64 a, u64 b, u64 c) {
    u64 d; asm("fma.rn.f32x2 %0, %1, %2, %3;" : "=l"(d) : "l"(a), "l"(b), "l"(c));
    return d;
}
__device__ __forceinline__ float2 upk(u64 a) {
    float2 r; asm("mov.b64 {%0, %1}, %2;" : "=f"(r.x), "=f"(r.y) : "l"(a)); return r;
}

__device__ float g_prm[64];                       // 5 frames x (M 3x3, b 3)
__device__ __align__(16) float g_f1[N_F1];
__device__ __align__(16) float g_f2[N_F2];
__device__ __align__(16) float g_p2[2*N_F2];      // conv2 ic-split partials
__device__ __align__(16) float g_f3[N_F3];        // plane layout [f][c][p]
__device__ __align__(16) float g_p3[2*N_F3];      // conv3 ic-split partials
__device__ __align__(16) float g_vol[32*N_VOX];   // avg channels only
__device__ __align__(16) float g_wt1t[64*27*32];  // wd1 transposed [ic][k][oc]
__device__ __align__(16) float g_sref[3*32*4800]; // [kd-slice][oc][p]
__device__ __align__(16) float g_h3[32*N_VOX];
__device__ __align__(16) float g_logits[N_VOX];   // ic 0..15 partial
__device__ __align__(16) float g_logits2[N_VOX];  // ic 16..31 partial

// --------------------------------------------------------------------------
// Combined: transpose wd1 (all threads) + projection setup (one thread).
__global__ void prep_kernel(const float* __restrict__ wd1,
                            const float* __restrict__ poses,
                            const float* __restrict__ intr)
{
    int i = blockIdx.x*blockDim.x + threadIdx.x;
    if (i < 55296) {
        int oc = i / 1728;          // 64*27
        int r  = i % 1728;
        int ic = r / 27, kk = r % 27;
        g_wt1t[(ic*27 + kk)*32 + oc] = wd1[i];
    }
    if (i != 0) return;
    // Gauss-Jordan inverse of poses[0]
    float A[4][8];
    for (int r = 0; r < 4; r++)
        for (int c = 0; c < 4; c++) {
            A[r][c]   = poses[r*4 + c];
            A[r][4+c] = (r == c) ? 1.f : 0.f;
        }
    for (int col = 0; col < 4; col++) {
        int piv = col; float best = fabsf(A[col][col]);
        for (int r = col+1; r < 4; r++) {
            float v = fabsf(A[r][col]);
            if (v > best) { best = v; piv = r; }
        }
        if (piv != col)
            for (int c = 0; c < 8; c++) {
                float t = A[col][c]; A[col][c] = A[piv][c]; A[piv][c] = t;
            }
        float inv = 1.f / A[col][col];
        for (int c = 0; c < 8; c++) A[col][c] *= inv;
        for (int r = 0; r < 4; r++) {
            if (r == col) continue;
            float fv = A[r][col];
            for (int c = 0; c < 8; c++) A[r][c] -= fv * A[col][c];
        }
    }
    float fx = intr[0]*0.25f, fy = intr[1]*0.25f;
    float cx = intr[2]*0.25f, cy = intr[3]*0.25f;
    float ifx = 1.f/fx, ify = 1.f/fy;
    for (int f = 0; f < 5; f++) {
        const float* P = poses + f*16;
        float G[3][4];
        for (int r = 0; r < 3; r++)
            for (int c = 0; c < 4; c++) {
                float s = 0.f;
                for (int k = 0; k < 4; k++) s += P[r*4+k] * A[k][4+c];
                G[r][c] = s;
            }
        float KR[3][4];
        for (int c = 0; c < 4; c++) {
            KR[0][c] = fx*G[0][c] + cx*G[2][c];
            KR[1][c] = fy*G[1][c] + cy*G[2][c];
            KR[2][c] = G[2][c];
        }
        for (int r = 0; r < 3; r++) {
            g_prm[f*12 + r*3 + 0] = KR[r][0]*ifx;
            g_prm[f*12 + r*3 + 1] = KR[r][1]*ify;
            g_prm[f*12 + r*3 + 2] = -KR[r][0]*cx*ifx - KR[r][1]*cy*ify + KR[r][2];
            g_prm[f*12 + 9 + r]   = KR[r][3];
        }
    }
}

// --------------------------------------------------------------------------
// conv1: 3->32, stride 2, SAME (pad lo=0, hi=1). Packed over oc pairs.
// Coalesced float2 loads; OOB raw value 127.5 -> normalized 0.
__global__ void __launch_bounds__(256) conv1_kernel(const float* __restrict__ img,
                             const float* __restrict__ w1,
                             const float* __restrict__ b1)
{
    __shared__ __align__(16) float ws[864];       // [(ic*9+k)*32 + oc]
    for (int i = threadIdx.x; i < 864; i += blockDim.x) {
        int oc = i / 27, r = i % 27;
        ws[r*32 + oc] = w1[i];
    }
    __syncthreads();
    int idx = blockIdx.x*blockDim.x + threadIdx.x;
    if (idx >= 5*240*320) return;
    int x = idx % 320, y = (idx/320) % 240, f = idx/(320*240);
    u64 acc[16];
    #pragma unroll
    for (int q = 0; q < 16; q++) acc[q] = 0ULL;
    const float* ip = img + (size_t)f*3*480*640;
    bool xok = (x < 319);
    #pragma unroll
    for (int ic = 0; ic < 3; ic++) {
        float2 a[3]; float c3[3];
        #pragma unroll
        for (int ky = 0; ky < 3; ky++) {
            int iy = 2*y + ky;
            if (iy < 480) {
                const float* rp = ip + (ic*480 + iy)*640 + 2*x;
                a[ky]  = *(const float2*)rp;
                c3[ky] = xok ? rp[2] : 127.5f;
            } else {
                a[ky] = make_float2(127.5f, 127.5f);
                c3[ky] = 127.5f;
            }
        }
        u64 pkv[9];
        #pragma unroll
        for (int ky = 0; ky < 3; ky++) {
            pkv[ky*3+0] = pk2(fmaf(a[ky].x, 2.f/255.f, -1.f));
            pkv[ky*3+1] = pk2(fmaf(a[ky].y, 2.f/255.f, -1.f));
            pkv[ky*3+2] = pk2(fmaf(c3[ky],  2.f/255.f, -1.f));
        }
        const ulonglong2* wb = (const ulonglong2*)(ws + ic*288);
        #pragma unroll
        for (int k = 0; k < 9; k++) {
            u64 vv = pkv[k];
            #pragma unroll
            for (int q = 0; q < 8; q++) {
                ulonglong2 wq = wb[k*8 + q];
                acc[2*q]   = f2fma(wq.x, vv, acc[2*q]);
                acc[2*q+1] = f2fma(wq.y, vv, acc[2*q+1]);
            }
        }
    }
    float* op = g_f1 + (size_t)f*32*240*320 + y*320 + x;
    #pragma unroll
    for (int q = 0; q < 16; q++) {
        float2 v = upk(acc[q]);
        op[(2*q)*76800]   = fmaxf(v.x + __ldg(b1 + 2*q), 0.f);
        op[(2*q+1)*76800] = fmaxf(v.y + __ldg(b1 + 2*q+1), 0.f);
    }
}

// --------------------------------------------------------------------------
// conv2 (stage 0) ic-split x2: 16 of 32 ics per block, 16 oc x 2 px tile.
// 192000 threads / 750 blocks. Raw partials to g_p2.
__global__ void __launch_bounds__(256) conv2sp_kernel(const float* __restrict__ w)
{
    int icg = blockIdx.x / 375;                   // uniform per block
    __shared__ __align__(16) float ws[4608];      // 16 ic x 9 k x 32 oc
    for (int i = threadIdx.x; i < 4608; i += 256) {
        int oc = i / 144, r = i % 144;            // r = icl*9 + k
        ws[r*32 + oc] = w[oc*288 + icg*144 + r];
    }
    __syncthreads();
    const int inH = 240, inW = 320, outH = 120, outW = 160;
    const int nXg = outW >> 1;
    int idx = (blockIdx.x % 375)*256 + threadIdx.x;   // 0..95999
    if (idx >= 5*outH*nXg*2) return;
    int xg  = idx % nXg;
    int ocg = (idx / nXg) & 1;
    int y   = (idx / (nXg*2)) % outH;
    int f   = idx / (nXg*2*outH);
    int oc0 = ocg*16;
    int ix0 = xg*4;
    int x0  = xg*2;

    u64 acc[8][2];
    #pragma unroll
    for (int p = 0; p < 8; p++) { acc[p][0] = 0ULL; acc[p][1] = 0ULL; }

    const float* ip = g_f1 + (size_t)f*32*inH*inW + (size_t)icg*16*inH*inW;
    bool tailok = (ix0 + 4 < inW);
    for (int icl = 0; icl < 16; icl++) {
        const float* icp = ip + icl*inH*inW;
        float4 A[3]; float C[3];
        #pragma unroll
        for (int ky = 0; ky < 3; ky++) {
            int iy = 2*y + ky;
            if (iy < inH) {
                const float* rp = icp + iy*inW + ix0;
                A[ky] = *(const float4*)rp;
                C[ky] = tailok ? rp[4] : 0.f;
            } else {
                A[ky] = make_float4(0.f, 0.f, 0.f, 0.f);
                C[ky] = 0.f;
            }
        }
        #pragma unroll
        for (int ky = 0; ky < 3; ky++) {
            u64 pkv[5];
            pkv[0] = pk2(A[ky].x); pkv[1] = pk2(A[ky].y); pkv[2] = pk2(A[ky].z);
            pkv[3] = pk2(A[ky].w); pkv[4] = pk2(C[ky]);
            const ulonglong2* wb = (const ulonglong2*)(ws + (icl*9 + ky*3)*32 + oc0);
            #pragma unroll
            for (int kx = 0; kx < 3; kx++) {
                u64 v0 = pkv[kx], v1 = pkv[kx+2];
                #pragma unroll
                for (int j = 0; j < 4; j++) {
                    ulonglong2 wq = wb[kx*8 + j];
                    acc[2*j][0]   = f2fma(wq.x, v0, acc[2*j][0]);
                    acc[2*j][1]   = f2fma(wq.x, v1, acc[2*j][1]);
                    acc[2*j+1][0] = f2fma(wq.y, v0, acc[2*j+1][0]);
                    acc[2*j+1][1] = f2fma(wq.y, v1, acc[2*j+1][1]);
                }
            }
        }
    }

    float* outp = g_p2 + (size_t)icg*N_F2;
    size_t obase = (size_t)f*32*outH*outW + y*outW + x0;
    #pragma unroll
    for (int p = 0; p < 8; p++) {
        float2 p0 = upk(acc[p][0]);
        float2 p1 = upk(acc[p][1]);
        *(float2*)(outp + obase + (size_t)(oc0 + 2*p)*outH*outW)
            = make_float2(p0.x, p1.x);
        *(float2*)(outp + obase + (size_t)(oc0 + 2*p + 1)*outH*outW)
            = make_float2(p0.y, p1.y);
    }
}

// --------------------------------------------------------------------------
// Combine conv2 partials: g_f2 = relu(p0 + p1 + bias).
__global__ void __launch_bounds__(256) comb2_kernel(const float* __restrict__ b)
{
    int j = blockIdx.x*256 + threadIdx.x;         // over 768000 float4
    if (j >= N_F2/4) return;
    int c = (j / 4800) % 32;                      // 120*160/4 = 4800 vec4/plane
    float4 A = *(const float4*)(g_p2 + 4*j);
    float4 B = *(const float4*)(g_p2 + N_F2 + 4*j);
    float bv = __ldg(b + c);
    float4 r;
    r.x = fmaxf(A.x + B.x + bv, 0.f);
    r.y = fmaxf(A.y + B.y + bv, 0.f);
    r.z = fmaxf(A.z + B.z + bv, 0.f);
    r.w = fmaxf(A.w + B.w + bv, 0.f);
    *(float4*)(g_f2 + 4*j) = r;
}

// --------------------------------------------------------------------------
// conv3 (stage 1) ic-split x2: 8 oc x 2 px, 96000 threads / 750 blocks.
__global__ void __launch_bounds__(128) conv3sp_kernel(const float* __restrict__ w)
{
    int icg = blockIdx.x / 375;                   // 0 or 1, uniform per block
    __shared__ __align__(16) float ws[4608];      // 16 ic x 9 k x 32 oc
    for (int i = threadIdx.x; i < 4608; i += 128) {
        int oc = i / 144, r = i % 144;            // r = icl*9 + k
        ws[r*32 + oc] = w[oc*288 + icg*144 + r];
    }
    __syncthreads();
    const int inH = 120, inW = 160, outH = 60, outW = 80;
    const int nXg = outW >> 1;
    int idx = (blockIdx.x % 375)*128 + threadIdx.x;   // 0..47999
    int xg  = idx % nXg;
    int ocg = (idx / nXg) & 3;
    int y   = (idx / (nXg*4)) % outH;
    int f   = idx / (nXg*4*outH);
    int oc0 = ocg*8;
    int ix0 = xg*4;
    int x0  = xg*2;

    u64 acc[4][2];
    #pragma unroll
    for (int p = 0; p < 4; p++) { acc[p][0] = 0ULL; acc[p][1] = 0ULL; }

    const float* ip = g_f2 + (size_t)f*32*inH*inW + (size_t)icg*16*inH*inW;
    bool tailok = (ix0 + 4 < inW);
    for (int icl = 0; icl < 16; icl++) {
        const float* icp = ip + icl*inH*inW;
        float4 A[3]; float C[3];
        #pragma unroll
        for (int ky = 0; ky < 3; ky++) {
            int iy = 2*y + ky;
            if (iy < inH) {
                const float* rp = icp + iy*inW + ix0;
                A[ky] = *(const float4*)rp;
                C[ky] = tailok ? rp[4] : 0.f;
            } else {
                A[ky] = make_float4(0.f, 0.f, 0.f, 0.f);
                C[ky] = 0.f;
            }
        }
        #pragma unroll
        for (int ky = 0; ky < 3; ky++) {
            u64 pkv[5];
            pkv[0] = pk2(A[ky].x); pkv[1] = pk2(A[ky].y); pkv[2] = pk2(A[ky].z);
            pkv[3] = pk2(A[ky].w); pkv[4] = pk2(C[ky]);
            const ulonglong2* wb = (const ulonglong2*)(ws + (icl*9 + ky*3)*32 + oc0);
            #pragma unroll
            for (int kx = 0; kx < 3; kx++) {
                u64 v0 = pkv[kx], v1 = pkv[kx+2];
                ulonglong2 wq0 = wb[kx*8];
                ulonglong2 wq1 = wb[kx*8 + 1];
                acc[0][0] = f2fma(wq0.x, v0, acc[0][0]);
                acc[0][1] = f2fma(wq0.x, v1, acc[0][1]);
                acc[1][0] = f2fma(wq0.y, v0, acc[1][0]);
                acc[1][1] = f2fma(wq0.y, v1, acc[1][1]);
                acc[2][0] = f2fma(wq1.x, v0, acc[2][0]);
                acc[2][1] = f2fma(wq1.x, v1, acc[2][1]);
                acc[3][0] = f2fma(wq1.y, v0, acc[3][0]);
                acc[3][1] = f2fma(wq1.y, v1, acc[3][1]);
            }
        }
    }

    float* outp = g_p3 + (size_t)icg*N_F3;
    size_t obase = (size_t)f*32*outH*outW + y*outW + x0;
    #pragma unroll
    for (int p = 0; p < 4; p++) {
        float2 p0 = upk(acc[p][0]);
        float2 p1 = upk(acc[p][1]);
        *(float2*)(outp + obase + (size_t)(oc0 + 2*p)*outH*outW)
            = make_float2(p0.x, p1.x);
        *(float2*)(outp + obase + (size_t)(oc0 + 2*p + 1)*outH*outW)
            = make_float2(p0.y, p1.y);
    }
}

// --------------------------------------------------------------------------
// Combine conv3 partials: g_f3 = relu(p0 + p1 + bias).
__global__ void __launch_bounds__(256) comb3_kernel(const float* __restrict__ b)
{
    int j = blockIdx.x*256 + threadIdx.x;         // over 192000 float4
    if (j >= N_F3/4) return;
    int c = (j / 1200) % 32;                      // 4800/4 = 1200 vec4/plane
    float4 A = *(const float4*)(g_p3 + 4*j);
    float4 B = *(const float4*)(g_p3 + N_F3 + 4*j);
    float bv = __ldg(b + c);
    float4 r;
    r.x = fmaxf(A.x + B.x + bv, 0.f);
    r.y = fmaxf(A.y + B.y + bv, 0.f);
    r.z = fmaxf(A.z + B.z + bv, 0.f);
    r.w = fmaxf(A.w + B.w + bv, 0.f);
    *(float4*)(g_f3 + 4*j) = r;
}

// --------------------------------------------------------------------------
// Cost volume, avg channels only (plane-layout gathers — wavefront-friendly).
__global__ void __launch_bounds__(256) build_volume_kernel()
{
    int idx = blockIdx.x*blockDim.x + threadIdx.x;
    if (idx >= N_VOX) return;
    int x  = idx % 80;
    int y  = (idx / 80) % 60;
    int dd = idx / 4800;
    float depth = 0.25f + 0.25f*(float)dd;
    float fxp = (float)x, fyp = (float)y;
    float sum[32];
    #pragma unroll
    for (int c = 0; c < 32; c++) sum[c] = 0.f;
    for (int f = 0; f < 5; f++) {
        const float* P = g_prm + f*12;
        float nu = depth*(P[0]*fxp + P[1]*fyp + P[2]) + P[9];
        float nv = depth*(P[3]*fxp + P[4]*fyp + P[5]) + P[10];
        float z  = depth*(P[6]*fxp + P[7]*fyp + P[8]) + P[11];
        float iz = 1.f/(z + 1e-8f);
        float u = nu*iz, v = nv*iz;
        float x0f = floorf(u), y0f = floorf(v);
        float wx = u - x0f, wy = v - y0f;
        int x0 = (int)x0f, y0 = (int)y0f;
        int xc0 = min(max(x0,   0), 79), xc1 = min(max(x0+1, 0), 79);
        int yc0 = min(max(y0,   0), 59), yc1 = min(max(y0+1, 0), 59);
        float valid = (u >= 0.f && u <= 79.f && v >= 0.f && v <= 59.f) ? 1.f : 0.f;
        float w00 = (1.f-wx)*(1.f-wy)*valid;
        float w10 = wx*(1.f-wy)*valid;
        float w01 = (1.f-wx)*wy*valid;
        float w11 = wx*wy*valid;
        const float* fb = g_f3 + (size_t)f*32*4800;
        int i00 = yc0*80 + xc0, i01 = yc0*80 + xc1;
        int i10 = yc1*80 + xc0, i11 = yc1*80 + xc1;
        #pragma unroll
        for (int c = 0; c < 32; c++) {
            const float* fc = fb + c*4800;
            sum[c] += w00*__ldg(fc+i00) + w10*__ldg(fc+i01)
                    + w01*__ldg(fc+i10) + w11*__ldg(fc+i11);
        }
    }
    #pragma unroll
    for (int c = 0; c < 32; c++)
        g_vol[c*N_VOX + idx] = sum[c] * 0.2f;
}

// --------------------------------------------------------------------------
// Ref-channel half of conv3d collapsed to 3 2D convs (per kd slice).
__global__ void __launch_bounds__(128) refconv_kernel()
{
    int s = blockIdx.y;                           // kd slice 0..2
    __shared__ __align__(16) float ws[9216];      // [ic][k2][oc]
    for (int i = threadIdx.x; i < 9216; i += 128) {
        int ic = i / 288, rem = i % 288;
        ws[i] = g_wt1t[ic*864 + s*288 + rem];
    }
    __syncthreads();
    int idx = blockIdx.x*128 + threadIdx.x;
    if (idx >= 4800) return;
    int x = idx % 80, y = idx / 80;
    u64 acc[16];
    #pragma unroll
    for (int q = 0; q < 16; q++) acc[q] = 0ULL;
    for (int ic = 0; ic < 32; ic++) {
        float raw[9];
        #pragma unroll
        for (int ky = 0; ky < 3; ky++) {
            int yy = y + ky - 1;
            #pragma unroll
            for (int kx = 0; kx < 3; kx++) {
                int xx = x + kx - 1;
                raw[ky*3+kx] = (yy >= 0 && yy < 60 && xx >= 0 && xx < 80)
                    ? __ldg(g_f3 + ic*4800 + yy*80 + xx) : 0.f;
            }
        }
        u64 pkv[9];
        #pragma unroll
        for (int k = 0; k < 9; k++) pkv[k] = pk2(raw[k]);
        const ulonglong2* wb = (const ulonglong2*)(ws + ic*288);
        #pragma unroll
        for (int k = 0; k < 9; k++) {
            u64 vv = pkv[k];
            #pragma unroll
            for (int q = 0; q < 8; q++) {
                ulonglong2 wq = wb[k*8 + q];
                acc[2*q]   = f2fma(wq.x, vv, acc[2*q]);
                acc[2*q+1] = f2fma(wq.y, vv, acc[2*q+1]);
            }
        }
    }
    #pragma unroll
    for (int q = 0; q < 16; q++) {
        float2 v = upk(acc[q]);
        g_sref[(s*32 + 2*q)*4800 + idx]   = v.x;
        g_sref[(s*32 + 2*q+1)*4800 + idx] = v.y;
    }
}

// --------------------------------------------------------------------------
// Main conv3d over avg channels; 8 oc x 8 px per thread, packed f32x2.
// block (10,4,6) = 240 threads, 2 blocks/SM -> 15 warps/SM; grid (32,10)
// = 320 blocks -> 1.08 waves. Rows batched per (ic,kd).
__global__ void __launch_bounds__(240, 2) conv3d_main_kernel(const float* __restrict__ bd1)
{
    int tx = threadIdx.x, ty = threadIdx.y, tz = threadIdx.z;
    int d  = blockIdx.x;
    int y  = blockIdx.y*6 + tz;
    int x0 = tx*8;
    int oc0 = ty*8;

    u64 acc[4][8];
    #pragma unroll
    for (int o2 = 0; o2 < 4; o2++) {
        int oe = oc0 + 2*o2;
        float be = __ldg(bd1 + oe);
        float bo = __ldg(bd1 + oe + 1);
        int p = y*80 + x0;
        float te[8], to[8];
        #pragma unroll
        for (int h = 0; h < 2; h++) {
            float4 e = *(const float4*)(g_sref + (32 + oe)*4800 + p + 4*h);
            float4 o = *(const float4*)(g_sref + (33 + oe)*4800 + p + 4*h);
            te[4*h+0] = e.x + be; te[4*h+1] = e.y + be;
            te[4*h+2] = e.z + be; te[4*h+3] = e.w + be;
            to[4*h+0] = o.x + bo; to[4*h+1] = o.y + bo;
            to[4*h+2] = o.z + bo; to[4*h+3] = o.w + bo;
        }
        if (d >= 1) {
            #pragma unroll
            for (int h = 0; h < 2; h++) {
                float4 e = *(const float4*)(g_sref + oe*4800 + p + 4*h);
                float4 o = *(const float4*)(g_sref + (oe+1)*4800 + p + 4*h);
                te[4*h+0] += e.x; te[4*h+1] += e.y; te[4*h+2] += e.z; te[4*h+3] += e.w;
                to[4*h+0] += o.x; to[4*h+1] += o.y; to[4*h+2] += o.z; to[4*h+3] += o.w;
            }
        }
        if (d <= 30) {
            #pragma unroll
            for (int h = 0; h < 2; h++) {
                float4 e = *(const float4*)(g_sref + (64+oe)*4800 + p + 4*h);
                float4 o = *(const float4*)(g_sref + (65+oe)*4800 + p + 4*h);
                te[4*h+0] += e.x; te[4*h+1] += e.y; te[4*h+2] += e.z; te[4*h+3] += e.w;
                to[4*h+0] += o.x; to[4*h+1] += o.y; to[4*h+2] += o.z; to[4*h+3] += o.w;
            }
        }
        #pragma unroll
        for (int xv = 0; xv < 8; xv++)
            acc[o2][xv] = pk(te[xv], to[xv]);
    }

    for (int ic = 0; ic < 32; ic++) {
        const float* ip = g_vol + (size_t)ic*N_VOX;
        const ulonglong2* wic = (const ulonglong2*)(g_wt1t + ((32+ic)*27)*32 + oc0);
        #pragma unroll
        for (int kd = 0; kd < 3; kd++) {
            int dz = d + kd - 1;
            if (dz < 0 || dz > 31) continue;      // uniform per block
            float rows[3][10];
            #pragma unroll
            for (int ky = 0; ky < 3; ky++) {
                int yy = y + ky - 1;
                if (yy >= 0 && yy < 60) {
                    const float* rp = ip + (dz*60 + yy)*80 + x0;
                    float4 m0 = *(const float4*)rp;
                    float4 m1 = *(const float4*)(rp + 4);
                    rows[ky][0] = (x0 > 0)      ? rp[-1] : 0.f;
                    rows[ky][1] = m0.x; rows[ky][2] = m0.y;
                    rows[ky][3] = m0.z; rows[ky][4] = m0.w;
                    rows[ky][5] = m1.x; rows[ky][6] = m1.y;
                    rows[ky][7] = m1.z; rows[ky][8] = m1.w;
                    rows[ky][9] = (x0 + 8 < 80) ? rp[8]  : 0.f;
                } else {
                    #pragma unroll
                    for (int j = 0; j < 10; j++) rows[ky][j] = 0.f;
                }
            }
            #pragma unroll
            for (int ky = 0; ky < 3; ky++) {
                u64 pkv[10];
                #pragma unroll
                for (int j = 0; j < 10; j++) pkv[j] = pk2(rows[ky][j]);
                int kb = kd*9 + ky*3;
                #pragma unroll
                for (int kx = 0; kx < 3; kx++) {
                    ulonglong2 wA = wic[(kb+kx)*8];
                    ulonglong2 wB = wic[(kb+kx)*8 + 1];
                    #pragma unroll
                    for (int xv = 0; xv < 8; xv++) {
                        u64 vv = pkv[kx + xv];
                        acc[0][xv] = f2fma(wA.x, vv, acc[0][xv]);
                        acc[1][xv] = f2fma(wA.y, vv, acc[1][xv]);
                        acc[2][xv] = f2fma(wB.x, vv, acc[2][xv]);
                        acc[3][xv] = f2fma(wB.y, vv, acc[3][xv]);
                    }
                }
            }
        }
    }

    size_t base = d*4800 + y*80 + x0;
    #pragma unroll
    for (int o2 = 0; o2 < 4; o2++) {
        float e[8], o[8];
        #pragma unroll
        for (int xv = 0; xv < 8; xv++) {
            float2 v = upk(acc[o2][xv]);
            e[xv] = fmaxf(v.x, 0.f);
            o[xv] = fmaxf(v.y, 0.f);
        }
        float* pe = g_h3 + (size_t)(oc0 + 2*o2)*N_VOX + base;
        float* po = g_h3 + (size_t)(oc0 + 2*o2 + 1)*N_VOX + base;
        *(float4*)pe       = make_float4(e[0], e[1], e[2], e[3]);
        *(float4*)(pe + 4) = make_float4(e[4], e[5], e[6], e[7]);
        *(float4*)po       = make_float4(o[0], o[1], o[2], o[3]);
        *(float4*)(po + 4) = make_float4(o[4], o[5], o[6], o[7]);
    }
}

// --------------------------------------------------------------------------
// Logits: 32->1 conv3d, ic-split x2 (76800 threads). Bias dropped — the
// scalar bias shifts all logits equally and cancels in softmax exactly.
__global__ void __launch_bounds__(128) logits_kernel(const float* __restrict__ wd2)
{
    int icg = blockIdx.x / 300;                   // 0 or 1, uniform per block
    __shared__ float ws[864];
    for (int i = threadIdx.x; i < 864; i += 128) ws[i] = wd2[i];
    __syncthreads();
    int idx = (blockIdx.x % 300)*128 + threadIdx.x;
    if (idx >= 38400) return;
    int xg = idx % 20;
    int y  = (idx / 20) % 60;
    int d  = idx / 1200;
    int x0 = xg*4;
    int ic0 = icg*16;

    u64 acc0 = 0ULL, acc1 = 0ULL;
    for (int icl = 0; icl < 16; icl++) {
        int ic = ic0 + icl;
        const float* ip = g_h3 + (size_t)ic*N_VOX;
        const float* wp = ws + ic*27;
        float rows[9][6];
        #pragma unroll
        for (int kd = 0; kd < 3; kd++) {
            int dz = d + kd - 1;
            #pragma unroll
            for (int ky = 0; ky < 3; ky++) {
                int yy = y + ky - 1;
                int r = kd*3 + ky;
                if (dz >= 0 && dz <= 31 && yy >= 0 && yy <= 59) {
                    const float* rp = ip + (dz*60 + yy)*80 + x0;
                    float4 m = *(const float4*)rp;
                    rows[r][0] = (x0 > 0)      ? rp[-1] : 0.f;
                    rows[r][1] = m.x; rows[r][2] = m.y;
                    rows[r][3] = m.z; rows[r][4] = m.w;
                    rows[r][5] = (x0 + 4 < 80) ? rp[4]  : 0.f;
                } else {
                    #pragma unroll
                    for (int j = 0; j < 6; j++) rows[r][j] = 0.f;
                }
            }
        }
        #pragma unroll
        for (int r = 0; r < 9; r++) {
            #pragma unroll
            for (int kx = 0; kx < 3; kx++) {
                u64 wv = pk2(wp[r*3 + kx]);
                acc0 = f2fma(wv, pk(rows[r][kx],   rows[r][kx+1]), acc0);
                acc1 = f2fma(wv, pk(rows[r][kx+2], rows[r][kx+3]), acc1);
            }
        }
    }
    float2 a = upk(acc0), bq = upk(acc1);
    float4 r = make_float4(a.x, a.y, bq.x, bq.y);
    float* dst = (icg == 0) ? g_logits : g_logits2;
    *(float4*)(dst + d*4800 + y*80 + x0) = r;
}

// --------------------------------------------------------------------------
__global__ void depth_out_kernel(float* __restrict__ out)
{
    int idx = blockIdx.x*blockDim.x + threadIdx.x;
    if (idx >= 4800) return;
    float l[32];
    float m = -1e30f;
    #pragma unroll
    for (int d = 0; d < 32; d++) {
        l[d] = g_logits[d*4800 + idx] + g_logits2[d*4800 + idx];
        m = fmaxf(m, l[d]);
    }
    float s = 0.f, num = 0.f;
    #pragma unroll
    for (int d = 0; d < 32; d++) {
        float e = expf(l[d] - m);
        s += e;
        num += (0.25f + 0.25f*(float)d) * e;
    }
    out[idx] = num / s;
}

// --------------------------------------------------------------------------
extern "C" void kernel_launch(void* const* d_in, const int* in_sizes, int n_in,
                              void* d_out, int out_size)
{
    const float* poses  = (const float*)d_in[0];
    const float* images = (const float*)d_in[1];
    const float* intr   = (const float*)d_in[2];
    const float* w1  = (const float*)d_in[3];
    const float* b1  = (const float*)d_in[4];
    const float* w2  = (const float*)d_in[5];
    const float* b2  = (const float*)d_in[6];
    const float* w3  = (const float*)d_in[7];
    const float* b3  = (const float*)d_in[8];
    const float* wd1 = (const float*)d_in[9];
    const float* bd1 = (const float*)d_in[10];
    const float* wd2 = (const float*)d_in[11];
    float* out = (float*)d_out;

    prep_kernel<<<216, 256>>>(wd1, poses, intr);
    conv1_kernel<<<1500, 256>>>(images, w1, b1);        // 5*240*320 threads
    conv2sp_kernel<<<750, 256>>>(w2);                   // stage 0 partials
    comb2_kernel<<<3000, 256>>>(b2);                    // sum + bias + relu
    conv3sp_kernel<<<750, 128>>>(w3);                   // stage 1 partials
    comb3_kernel<<<750, 256>>>(b3);                     // sum + bias + relu
    build_volume_kernel<<<600, 256>>>();                // 153600
    refconv_kernel<<<dim3(38, 3), 128>>>();             // 4800 x 3 slices
    conv3d_main_kernel<<<dim3(32, 10), dim3(10, 4, 6)>>>(bd1);
    logits_kernel<<<600, 128>>>(wd2);                   // ic-split x2
    depth_out_kernel<<<19, 256>>>(out);                 // 4800
}

// round 17
// speedup vs baseline: 1.1411x; 1.1411x over previous
#include <cuda_runtime.h>
#include <math.h>

// ---------------------------------------------------------------------------
// DepthModule: plane-sweep stereo depth network, fp32 with packed f32x2 FMA.
// R17: revert conv3d_main to (120,3) + conv2 to non-split (R15 measured-best);
//      keep logits ic-split x2 (bias cancels in softmax).
// ---------------------------------------------------------------------------

#define N_F1 (5*32*240*320)
#define N_F2 (5*32*120*160)
#define N_F3 (5*32*60*80)
#define N_VOX (32*60*80)          // 153600

typedef unsigned long long u64;

__device__ __forceinline__ u64 pk(float lo, float hi) {
    u64 r; asm("mov.b64 %0, {%1, %2};" : "=l"(r) : "f"(lo), "f"(hi)); return r;
}
__device__ __forceinline__ u64 pk2(float v) { return pk(v, v); }
__device__ __forceinline__ u64 f2fma(u64 a, u64 b, u64 c) {
    u64 d; asm("fma.rn.f32x2 %0, %1, %2, %3;" : "=l"(d) : "l"(a), "l"(b), "l"(c));
    return d;
}
__device__ __forceinline__ float2 upk(u64 a) {
    float2 r; asm("mov.b64 {%0, %1}, %2;" : "=f"(r.x), "=f"(r.y) : "l"(a)); return r;
}

__device__ float g_prm[64];                       // 5 frames x (M 3x3, b 3)
__device__ __align__(16) float g_f1[N_F1];
__device__ __align__(16) float g_f2[N_F2];
__device__ __align__(16) float g_f3[N_F3];        // plane layout [f][c][p]
__device__ __align__(16) float g_p3[2*N_F3];      // conv3 ic-split partials
__device__ __align__(16) float g_vol[32*N_VOX];   // avg channels only
__device__ __align__(16) float g_wt1t[64*27*32];  // wd1 transposed [ic][k][oc]
__device__ __align__(16) float g_sref[3*32*4800]; // [kd-slice][oc][p]
__device__ __align__(16) float g_h3[32*N_VOX];
__device__ __align__(16) float g_logits[N_VOX];   // ic 0..15 partial
__device__ __align__(16) float g_logits2[N_VOX];  // ic 16..31 partial

// --------------------------------------------------------------------------
// Combined: transpose wd1 (all threads) + projection setup (one thread).
__global__ void prep_kernel(const float* __restrict__ wd1,
                            const float* __restrict__ poses,
                            const float* __restrict__ intr)
{
    int i = blockIdx.x*blockDim.x + threadIdx.x;
    if (i < 55296) {
        int oc = i / 1728;          // 64*27
        int r  = i % 1728;
        int ic = r / 27, kk = r % 27;
        g_wt1t[(ic*27 + kk)*32 + oc] = wd1[i];
    }
    if (i != 0) return;
    // Gauss-Jordan inverse of poses[0]
    float A[4][8];
    for (int r = 0; r < 4; r++)
        for (int c = 0; c < 4; c++) {
            A[r][c]   = poses[r*4 + c];
            A[r][4+c] = (r == c) ? 1.f : 0.f;
        }
    for (int col = 0; col < 4; col++) {
        int piv = col; float best = fabsf(A[col][col]);
        for (int r = col+1; r < 4; r++) {
            float v = fabsf(A[r][col]);
            if (v > best) { best = v; piv = r; }
        }
        if (piv != col)
            for (int c = 0; c < 8; c++) {
                float t = A[col][c]; A[col][c] = A[piv][c]; A[piv][c] = t;
            }
        float inv = 1.f / A[col][col];
        for (int c = 0; c < 8; c++) A[col][c] *= inv;
        for (int r = 0; r < 4; r++) {
            if (r == col) continue;
            float fv = A[r][col];
            for (int c = 0; c < 8; c++) A[r][c] -= fv * A[col][c];
        }
    }
    float fx = intr[0]*0.25f, fy = intr[1]*0.25f;
    float cx = intr[2]*0.25f, cy = intr[3]*0.25f;
    float ifx = 1.f/fx, ify = 1.f/fy;
    for (int f = 0; f < 5; f++) {
        const float* P = poses + f*16;
        float G[3][4];
        for (int r = 0; r < 3; r++)
            for (int c = 0; c < 4; c++) {
                float s = 0.f;
                for (int k = 0; k < 4; k++) s += P[r*4+k] * A[k][4+c];
                G[r][c] = s;
            }
        float KR[3][4];
        for (int c = 0; c < 4; c++) {
            KR[0][c] = fx*G[0][c] + cx*G[2][c];
            KR[1][c] = fy*G[1][c] + cy*G[2][c];
            KR[2][c] = G[2][c];
        }
        for (int r = 0; r < 3; r++) {
            g_prm[f*12 + r*3 + 0] = KR[r][0]*ifx;
            g_prm[f*12 + r*3 + 1] = KR[r][1]*ify;
            g_prm[f*12 + r*3 + 2] = -KR[r][0]*cx*ifx - KR[r][1]*cy*ify + KR[r][2];
            g_prm[f*12 + 9 + r]   = KR[r][3];
        }
    }
}

// --------------------------------------------------------------------------
// conv1: 3->32, stride 2, SAME (pad lo=0, hi=1). Packed over oc pairs.
// Coalesced float2 loads; OOB raw value 127.5 -> normalized 0.
__global__ void __launch_bounds__(256) conv1_kernel(const float* __restrict__ img,
                             const float* __restrict__ w1,
                             const float* __restrict__ b1)
{
    __shared__ __align__(16) float ws[864];       // [(ic*9+k)*32 + oc]
    for (int i = threadIdx.x; i < 864; i += blockDim.x) {
        int oc = i / 27, r = i % 27;
        ws[r*32 + oc] = w1[i];
    }
    __syncthreads();
    int idx = blockIdx.x*blockDim.x + threadIdx.x;
    if (idx >= 5*240*320) return;
    int x = idx % 320, y = (idx/320) % 240, f = idx/(320*240);
    u64 acc[16];
    #pragma unroll
    for (int q = 0; q < 16; q++) acc[q] = 0ULL;
    const float* ip = img + (size_t)f*3*480*640;
    bool xok = (x < 319);
    #pragma unroll
    for (int ic = 0; ic < 3; ic++) {
        float2 a[3]; float c3[3];
        #pragma unroll
        for (int ky = 0; ky < 3; ky++) {
            int iy = 2*y + ky;
            if (iy < 480) {
                const float* rp = ip + (ic*480 + iy)*640 + 2*x;
                a[ky]  = *(const float2*)rp;
                c3[ky] = xok ? rp[2] : 127.5f;
            } else {
                a[ky] = make_float2(127.5f, 127.5f);
                c3[ky] = 127.5f;
            }
        }
        u64 pkv[9];
        #pragma unroll
        for (int ky = 0; ky < 3; ky++) {
            pkv[ky*3+0] = pk2(fmaf(a[ky].x, 2.f/255.f, -1.f));
            pkv[ky*3+1] = pk2(fmaf(a[ky].y, 2.f/255.f, -1.f));
            pkv[ky*3+2] = pk2(fmaf(c3[ky],  2.f/255.f, -1.f));
        }
        const ulonglong2* wb = (const ulonglong2*)(ws + ic*288);
        #pragma unroll
        for (int k = 0; k < 9; k++) {
            u64 vv = pkv[k];
            #pragma unroll
            for (int q = 0; q < 8; q++) {
                ulonglong2 wq = wb[k*8 + q];
                acc[2*q]   = f2fma(wq.x, vv, acc[2*q]);
                acc[2*q+1] = f2fma(wq.y, vv, acc[2*q+1]);
            }
        }
    }
    float* op = g_f1 + (size_t)f*32*240*320 + y*320 + x;
    #pragma unroll
    for (int q = 0; q < 16; q++) {
        float2 v = upk(acc[q]);
        op[(2*q)*76800]   = fmaxf(v.x + __ldg(b1 + 2*q), 0.f);
        op[(2*q+1)*76800] = fmaxf(v.y + __ldg(b1 + 2*q+1), 0.f);
    }
}

// --------------------------------------------------------------------------
// conv2 (stage 0): 32->32, stride 2, g_f1 -> g_f2. 16 oc x 2 px, batched rows.
__global__ void __launch_bounds__(256) conv2s_kernel(const float* __restrict__ w,
                              const float* __restrict__ b)
{
    __shared__ __align__(16) float ws[9216];      // [(ic*9+k)*32 + oc]
    for (int i = threadIdx.x; i < 9216; i += 256) {
        int oc = i / 288, r = i % 288;
        ws[r*32 + oc] = w[i];
    }
    __syncthreads();
    const float* in = g_f1;
    float* out      = g_f2;
    const int inH = 240, inW = 320, outH = 120, outW = 160;
    const int nXg = outW >> 1;                    // 2 px per thread
    int idx = blockIdx.x*256 + threadIdx.x;
    int total = 5*outH*nXg*2;                     // x 2 oc-groups
    if (idx >= total) return;
    int xg  = idx % nXg;
    int ocg = (idx / nXg) & 1;
    int y   = (idx / (nXg*2)) % outH;
    int f   = idx / (nXg*2*outH);
    int oc0 = ocg*16;
    int ix0 = xg*4;
    int x0  = xg*2;

    u64 acc[8][2];
    #pragma unroll
    for (int p = 0; p < 8; p++) { acc[p][0] = 0ULL; acc[p][1] = 0ULL; }

    const float* ip = in + (size_t)f*32*inH*inW;
    bool tailok = (ix0 + 4 < inW);
    for (int ic = 0; ic < 32; ic++) {
        const float* icp = ip + ic*inH*inW;
        float4 A[3]; float C[3];
        #pragma unroll
        for (int ky = 0; ky < 3; ky++) {
            int iy = 2*y + ky;
            if (iy < inH) {
                const float* rp = icp + iy*inW + ix0;
                A[ky] = *(const float4*)rp;
                C[ky] = tailok ? rp[4] : 0.f;
            } else {
                A[ky] = make_float4(0.f, 0.f, 0.f, 0.f);
                C[ky] = 0.f;
            }
        }
        #pragma unroll
        for (int ky = 0; ky < 3; ky++) {
            u64 pkv[5];
            pkv[0] = pk2(A[ky].x); pkv[1] = pk2(A[ky].y); pkv[2] = pk2(A[ky].z);
            pkv[3] = pk2(A[ky].w); pkv[4] = pk2(C[ky]);
            const ulonglong2* wb = (const ulonglong2*)(ws + (ic*9 + ky*3)*32 + oc0);
            #pragma unroll
            for (int kx = 0; kx < 3; kx++) {
                u64 v0 = pkv[kx], v1 = pkv[kx+2];
                #pragma unroll
                for (int j = 0; j < 4; j++) {
                    ulonglong2 wq = wb[kx*8 + j];
                    acc[2*j][0]   = f2fma(wq.x, v0, acc[2*j][0]);
                    acc[2*j][1]   = f2fma(wq.x, v1, acc[2*j][1]);
                    acc[2*j+1][0] = f2fma(wq.y, v0, acc[2*j+1][0]);
                    acc[2*j+1][1] = f2fma(wq.y, v1, acc[2*j+1][1]);
                }
            }
        }
    }

    size_t obase = (size_t)f*32*outH*outW + y*outW + x0;
    #pragma unroll
    for (int p = 0; p < 8; p++) {
        float be = __ldg(b + oc0 + 2*p);
        float bo = __ldg(b + oc0 + 2*p + 1);
        float2 p0 = upk(acc[p][0]);
        float2 p1 = upk(acc[p][1]);
        float2 re = make_float2(fmaxf(p0.x + be, 0.f), fmaxf(p1.x + be, 0.f));
        float2 ro = make_float2(fmaxf(p0.y + bo, 0.f), fmaxf(p1.y + bo, 0.f));
        *(float2*)(out + obase + (size_t)(oc0 + 2*p)*outH*outW)     = re;
        *(float2*)(out + obase + (size_t)(oc0 + 2*p + 1)*outH*outW) = ro;
    }
}

// --------------------------------------------------------------------------
// conv3 (stage 1) ic-split x2: 8 oc x 2 px, 96000 threads / 750 blocks.
__global__ void __launch_bounds__(128) conv3sp_kernel(const float* __restrict__ w)
{
    int icg = blockIdx.x / 375;                   // 0 or 1, uniform per block
    __shared__ __align__(16) float ws[4608];      // 16 ic x 9 k x 32 oc
    for (int i = threadIdx.x; i < 4608; i += 128) {
        int oc = i / 144, r = i % 144;            // r = icl*9 + k
        ws[r*32 + oc] = w[oc*288 + icg*144 + r];
    }
    __syncthreads();
    const int inH = 120, inW = 160, outH = 60, outW = 80;
    const int nXg = outW >> 1;
    int idx = (blockIdx.x % 375)*128 + threadIdx.x;   // 0..47999
    int xg  = idx % nXg;
    int ocg = (idx / nXg) & 3;
    int y   = (idx / (nXg*4)) % outH;
    int f   = idx / (nXg*4*outH);
    int oc0 = ocg*8;
    int ix0 = xg*4;
    int x0  = xg*2;

    u64 acc[4][2];
    #pragma unroll
    for (int p = 0; p < 4; p++) { acc[p][0] = 0ULL; acc[p][1] = 0ULL; }

    const float* ip = g_f2 + (size_t)f*32*inH*inW + (size_t)icg*16*inH*inW;
    bool tailok = (ix0 + 4 < inW);
    for (int icl = 0; icl < 16; icl++) {
        const float* icp = ip + icl*inH*inW;
        float4 A[3]; float C[3];
        #pragma unroll
        for (int ky = 0; ky < 3; ky++) {
            int iy = 2*y + ky;
            if (iy < inH) {
                const float* rp = icp + iy*inW + ix0;
                A[ky] = *(const float4*)rp;
                C[ky] = tailok ? rp[4] : 0.f;
            } else {
                A[ky] = make_float4(0.f, 0.f, 0.f, 0.f);
                C[ky] = 0.f;
            }
        }
        #pragma unroll
        for (int ky = 0; ky < 3; ky++) {
            u64 pkv[5];
            pkv[0] = pk2(A[ky].x); pkv[1] = pk2(A[ky].y); pkv[2] = pk2(A[ky].z);
            pkv[3] = pk2(A[ky].w); pkv[4] = pk2(C[ky]);
            const ulonglong2* wb = (const ulonglong2*)(ws + (icl*9 + ky*3)*32 + oc0);
            #pragma unroll
            for (int kx = 0; kx < 3; kx++) {
                u64 v0 = pkv[kx], v1 = pkv[kx+2];
                ulonglong2 wq0 = wb[kx*8];
                ulonglong2 wq1 = wb[kx*8 + 1];
                acc[0][0] = f2fma(wq0.x, v0, acc[0][0]);
                acc[0][1] = f2fma(wq0.x, v1, acc[0][1]);
                acc[1][0] = f2fma(wq0.y, v0, acc[1][0]);
                acc[1][1] = f2fma(wq0.y, v1, acc[1][1]);
                acc[2][0] = f2fma(wq1.x, v0, acc[2][0]);
                acc[2][1] = f2fma(wq1.x, v1, acc[2][1]);
                acc[3][0] = f2fma(wq1.y, v0, acc[3][0]);
                acc[3][1] = f2fma(wq1.y, v1, acc[3][1]);
            }
        }
    }

    float* outp = g_p3 + (size_t)icg*N_F3;
    size_t obase = (size_t)f*32*outH*outW + y*outW + x0;
    #pragma unroll
    for (int p = 0; p < 4; p++) {
        float2 p0 = upk(acc[p][0]);
        float2 p1 = upk(acc[p][1]);
        *(float2*)(outp + obase + (size_t)(oc0 + 2*p)*outH*outW)
            = make_float2(p0.x, p1.x);
        *(float2*)(outp + obase + (size_t)(oc0 + 2*p + 1)*outH*outW)
            = make_float2(p0.y, p1.y);
    }
}

// --------------------------------------------------------------------------
// Combine conv3 partials: g_f3 = relu(p0 + p1 + bias).
__global__ void __launch_bounds__(256) comb3_kernel(const float* __restrict__ b)
{
    int j = blockIdx.x*256 + threadIdx.x;         // over 192000 float4
    if (j >= N_F3/4) return;
    int c = (j / 1200) % 32;                      // 4800/4 = 1200 vec4/plane
    float4 A = *(const float4*)(g_p3 + 4*j);
    float4 B = *(const float4*)(g_p3 + N_F3 + 4*j);
    float bv = __ldg(b + c);
    float4 r;
    r.x = fmaxf(A.x + B.x + bv, 0.f);
    r.y = fmaxf(A.y + B.y + bv, 0.f);
    r.z = fmaxf(A.z + B.z + bv, 0.f);
    r.w = fmaxf(A.w + B.w + bv, 0.f);
    *(float4*)(g_f3 + 4*j) = r;
}

// --------------------------------------------------------------------------
// Cost volume, avg channels only (plane-layout gathers — wavefront-friendly).
__global__ void __launch_bounds__(256) build_volume_kernel()
{
    int idx = blockIdx.x*blockDim.x + threadIdx.x;
    if (idx >= N_VOX) return;
    int x  = idx % 80;
    int y  = (idx / 80) % 60;
    int dd = idx / 4800;
    float depth = 0.25f + 0.25f*(float)dd;
    float fxp = (float)x, fyp = (float)y;
    float sum[32];
    #pragma unroll
    for (int c = 0; c < 32; c++) sum[c] = 0.f;
    for (int f = 0; f < 5; f++) {
        const float* P = g_prm + f*12;
        float nu = depth*(P[0]*fxp + P[1]*fyp + P[2]) + P[9];
        float nv = depth*(P[3]*fxp + P[4]*fyp + P[5]) + P[10];
        float z  = depth*(P[6]*fxp + P[7]*fyp + P[8]) + P[11];
        float iz = 1.f/(z + 1e-8f);
        float u = nu*iz, v = nv*iz;
        float x0f = floorf(u), y0f = floorf(v);
        float wx = u - x0f, wy = v - y0f;
        int x0 = (int)x0f, y0 = (int)y0f;
        int xc0 = min(max(x0,   0), 79), xc1 = min(max(x0+1, 0), 79);
        int yc0 = min(max(y0,   0), 59), yc1 = min(max(y0+1, 0), 59);
        float valid = (u >= 0.f && u <= 79.f && v >= 0.f && v <= 59.f) ? 1.f : 0.f;
        float w00 = (1.f-wx)*(1.f-wy)*valid;
        float w10 = wx*(1.f-wy)*valid;
        float w01 = (1.f-wx)*wy*valid;
        float w11 = wx*wy*valid;
        const float* fb = g_f3 + (size_t)f*32*4800;
        int i00 = yc0*80 + xc0, i01 = yc0*80 + xc1;
        int i10 = yc1*80 + xc0, i11 = yc1*80 + xc1;
        #pragma unroll
        for (int c = 0; c < 32; c++) {
            const float* fc = fb + c*4800;
            sum[c] += w00*__ldg(fc+i00) + w10*__ldg(fc+i01)
                    + w01*__ldg(fc+i10) + w11*__ldg(fc+i11);
        }
    }
    #pragma unroll
    for (int c = 0; c < 32; c++)
        g_vol[c*N_VOX + idx] = sum[c] * 0.2f;
}

// --------------------------------------------------------------------------
// Ref-channel half of conv3d collapsed to 3 2D convs (per kd slice).
__global__ void __launch_bounds__(128) refconv_kernel()
{
    int s = blockIdx.y;                           // kd slice 0..2
    __shared__ __align__(16) float ws[9216];      // [ic][k2][oc]
    for (int i = threadIdx.x; i < 9216; i += 128) {
        int ic = i / 288, rem = i % 288;
        ws[i] = g_wt1t[ic*864 + s*288 + rem];
    }
    __syncthreads();
    int idx = blockIdx.x*128 + threadIdx.x;
    if (idx >= 4800) return;
    int x = idx % 80, y = idx / 80;
    u64 acc[16];
    #pragma unroll
    for (int q = 0; q < 16; q++) acc[q] = 0ULL;
    for (int ic = 0; ic < 32; ic++) {
        float raw[9];
        #pragma unroll
        for (int ky = 0; ky < 3; ky++) {
            int yy = y + ky - 1;
            #pragma unroll
            for (int kx = 0; kx < 3; kx++) {
                int xx = x + kx - 1;
                raw[ky*3+kx] = (yy >= 0 && yy < 60 && xx >= 0 && xx < 80)
                    ? __ldg(g_f3 + ic*4800 + yy*80 + xx) : 0.f;
            }
        }
        u64 pkv[9];
        #pragma unroll
        for (int k = 0; k < 9; k++) pkv[k] = pk2(raw[k]);
        const ulonglong2* wb = (const ulonglong2*)(ws + ic*288);
        #pragma unroll
        for (int k = 0; k < 9; k++) {
            u64 vv = pkv[k];
            #pragma unroll
            for (int q = 0; q < 8; q++) {
                ulonglong2 wq = wb[k*8 + q];
                acc[2*q]   = f2fma(wq.x, vv, acc[2*q]);
                acc[2*q+1] = f2fma(wq.y, vv, acc[2*q+1]);
            }
        }
    }
    #pragma unroll
    for (int q = 0; q < 16; q++) {
        float2 v = upk(acc[q]);
        g_sref[(s*32 + 2*q)*4800 + idx]   = v.x;
        g_sref[(s*32 + 2*q+1)*4800 + idx] = v.y;
    }
}

// --------------------------------------------------------------------------
// Main conv3d over avg channels; 8 oc x 8 px per thread, packed f32x2.
// block (10,4,3) = 120 threads, grid (32,20). Rows batched per (ic,kd).
// (R15 measured-best shape; (240,2) reshape regressed — suspected spills.)
__global__ void __launch_bounds__(120, 3) conv3d_main_kernel(const float* __restrict__ bd1)
{
    int tx = threadIdx.x, ty = threadIdx.y, tz = threadIdx.z;
    int d  = blockIdx.x;
    int y  = blockIdx.y*3 + tz;
    int x0 = tx*8;
    int oc0 = ty*8;

    u64 acc[4][8];
    #pragma unroll
    for (int o2 = 0; o2 < 4; o2++) {
        int oe = oc0 + 2*o2;
        float be = __ldg(bd1 + oe);
        float bo = __ldg(bd1 + oe + 1);
        int p = y*80 + x0;
        float te[8], to[8];
        #pragma unroll
        for (int h = 0; h < 2; h++) {
            float4 e = *(const float4*)(g_sref + (32 + oe)*4800 + p + 4*h);
            float4 o = *(const float4*)(g_sref + (33 + oe)*4800 + p + 4*h);
            te[4*h+0] = e.x + be; te[4*h+1] = e.y + be;
            te[4*h+2] = e.z + be; te[4*h+3] = e.w + be;
            to[4*h+0] = o.x + bo; to[4*h+1] = o.y + bo;
            to[4*h+2] = o.z + bo; to[4*h+3] = o.w + bo;
        }
        if (d >= 1) {
            #pragma unroll
            for (int h = 0; h < 2; h++) {
                float4 e = *(const float4*)(g_sref + oe*4800 + p + 4*h);
                float4 o = *(const float4*)(g_sref + (oe+1)*4800 + p + 4*h);
                te[4*h+0] += e.x; te[4*h+1] += e.y; te[4*h+2] += e.z; te[4*h+3] += e.w;
                to[4*h+0] += o.x; to[4*h+1] += o.y; to[4*h+2] += o.z; to[4*h+3] += o.w;
            }
        }
        if (d <= 30) {
            #pragma unroll
            for (int h = 0; h < 2; h++) {
                float4 e = *(const float4*)(g_sref + (64+oe)*4800 + p + 4*h);
                float4 o = *(const float4*)(g_sref + (65+oe)*4800 + p + 4*h);
                te[4*h+0] += e.x; te[4*h+1] += e.y; te[4*h+2] += e.z; te[4*h+3] += e.w;
                to[4*h+0] += o.x; to[4*h+1] += o.y; to[4*h+2] += o.z; to[4*h+3] += o.w;
            }
        }
        #pragma unroll
        for (int xv = 0; xv < 8; xv++)
            acc[o2][xv] = pk(te[xv], to[xv]);
    }

    for (int ic = 0; ic < 32; ic++) {
        const float* ip = g_vol + (size_t)ic*N_VOX;
        const ulonglong2* wic = (const ulonglong2*)(g_wt1t + ((32+ic)*27)*32 + oc0);
        #pragma unroll
        for (int kd = 0; kd < 3; kd++) {
            int dz = d + kd - 1;
            if (dz < 0 || dz > 31) continue;      // uniform per block
            float rows[3][10];
            #pragma unroll
            for (int ky = 0; ky < 3; ky++) {
                int yy = y + ky - 1;
                if (yy >= 0 && yy < 60) {
                    const float* rp = ip + (dz*60 + yy)*80 + x0;
                    float4 m0 = *(const float4*)rp;
                    float4 m1 = *(const float4*)(rp + 4);
                    rows[ky][0] = (x0 > 0)      ? rp[-1] : 0.f;
                    rows[ky][1] = m0.x; rows[ky][2] = m0.y;
                    rows[ky][3] = m0.z; rows[ky][4] = m0.w;
                    rows[ky][5] = m1.x; rows[ky][6] = m1.y;
                    rows[ky][7] = m1.z; rows[ky][8] = m1.w;
                    rows[ky][9] = (x0 + 8 < 80) ? rp[8]  : 0.f;
                } else {
                    #pragma unroll
                    for (int j = 0; j < 10; j++) rows[ky][j] = 0.f;
                }
            }
            #pragma unroll
            for (int ky = 0; ky < 3; ky++) {
                u64 pkv[10];
                #pragma unroll
                for (int j = 0; j < 10; j++) pkv[j] = pk2(rows[ky][j]);
                int kb = kd*9 + ky*3;
                #pragma unroll
                for (int kx = 0; kx < 3; kx++) {
                    ulonglong2 wA = wic[(kb+kx)*8];
                    ulonglong2 wB = wic[(kb+kx)*8 + 1];
                    #pragma unroll
                    for (int xv = 0; xv < 8; xv++) {
                        u64 vv = pkv[kx + xv];
                        acc[0][xv] = f2fma(wA.x, vv, acc[0][xv]);
                        acc[1][xv] = f2fma(wA.y, vv, acc[1][xv]);
                        acc[2][xv] = f2fma(wB.x, vv, acc[2][xv]);
                        acc[3][xv] = f2fma(wB.y, vv, acc[3][xv]);
                    }
                }
            }
        }
    }

    size_t base = d*4800 + y*80 + x0;
    #pragma unroll
    for (int o2 = 0; o2 < 4; o2++) {
        float e[8], o[8];
        #pragma unroll
        for (int xv = 0; xv < 8; xv++) {
            float2 v = upk(acc[o2][xv]);
            e[xv] = fmaxf(v.x, 0.f);
            o[xv] = fmaxf(v.y, 0.f);
        }
        float* pe = g_h3 + (size_t)(oc0 + 2*o2)*N_VOX + base;
        float* po = g_h3 + (size_t)(oc0 + 2*o2 + 1)*N_VOX + base;
        *(float4*)pe       = make_float4(e[0], e[1], e[2], e[3]);
        *(float4*)(pe + 4) = make_float4(e[4], e[5], e[6], e[7]);
        *(float4*)po       = make_float4(o[0], o[1], o[2], o[3]);
        *(float4*)(po + 4) = make_float4(o[4], o[5], o[6], o[7]);
    }
}

// --------------------------------------------------------------------------
// Logits: 32->1 conv3d, ic-split x2 (76800 threads). Bias dropped — the
// scalar bias shifts all logits equally and cancels in softmax exactly.
__global__ void __launch_bounds__(128) logits_kernel(const float* __restrict__ wd2)
{
    int icg = blockIdx.x / 300;                   // 0 or 1, uniform per block
    __shared__ float ws[864];
    for (int i = threadIdx.x; i < 864; i += 128) ws[i] = wd2[i];
    __syncthreads();
    int idx = (blockIdx.x % 300)*128 + threadIdx.x;
    if (idx >= 38400) return;
    int xg = idx % 20;
    int y  = (idx / 20) % 60;
    int d  = idx / 1200;
    int x0 = xg*4;
    int ic0 = icg*16;

    u64 acc0 = 0ULL, acc1 = 0ULL;
    for (int icl = 0; icl < 16; icl++) {
        int ic = ic0 + icl;
        const float* ip = g_h3 + (size_t)ic*N_VOX;
        const float* wp = ws + ic*27;
        float rows[9][6];
        #pragma unroll
        for (int kd = 0; kd < 3; kd++) {
            int dz = d + kd - 1;
            #pragma unroll
            for (int ky = 0; ky < 3; ky++) {
                int yy = y + ky - 1;
                int r = kd*3 + ky;
                if (dz >= 0 && dz <= 31 && yy >= 0 && yy <= 59) {
                    const float* rp = ip + (dz*60 + yy)*80 + x0;
                    float4 m = *(const float4*)rp;
                    rows[r][0] = (x0 > 0)      ? rp[-1] : 0.f;
                    rows[r][1] = m.x; rows[r][2] = m.y;
                    rows[r][3] = m.z; rows[r][4] = m.w;
                    rows[r][5] = (x0 + 4 < 80) ? rp[4]  : 0.f;
                } else {
                    #pragma unroll
                    for (int j = 0; j < 6; j++) rows[r][j] = 0.f;
                }
            }
        }
        #pragma unroll
        for (int r = 0; r < 9; r++) {
            #pragma unroll
            for (int kx = 0; kx < 3; kx++) {
                u64 wv = pk2(wp[r*3 + kx]);
                acc0 = f2fma(wv, pk(rows[r][kx],   rows[r][kx+1]), acc0);
                acc1 = f2fma(wv, pk(rows[r][kx+2], rows[r][kx+3]), acc1);
            }
        }
    }
    float2 a = upk(acc0), bq = upk(acc1);
    float4 r = make_float4(a.x, a.y, bq.x, bq.y);
    float* dst = (icg == 0) ? g_logits : g_logits2;
    *(float4*)(dst + d*4800 + y*80 + x0) = r;
}

// --------------------------------------------------------------------------
__global__ void depth_out_kernel(float* __restrict__ out)
{
    int idx = blockIdx.x*blockDim.x + threadIdx.x;
    if (idx >= 4800) return;
    float l[32];
    float m = -1e30f;
    #pragma unroll
    for (int d = 0; d < 32; d++) {
        l[d] = g_logits[d*4800 + idx] + g_logits2[d*4800 + idx];
        m = fmaxf(m, l[d]);
    }
    float s = 0.f, num = 0.f;
    #pragma unroll
    for (int d = 0; d < 32; d++) {
        float e = expf(l[d] - m);
        s += e;
        num += (0.25f + 0.25f*(float)d) * e;
    }
    out[idx] = num / s;
}

// --------------------------------------------------------------------------
extern "C" void kernel_launch(void* const* d_in, const int* in_sizes, int n_in,
                              void* d_out, int out_size)
{
    const float* poses  = (const float*)d_in[0];
    const float* images = (const float*)d_in[1];
    const float* intr   = (const float*)d_in[2];
    const float* w1  = (const float*)d_in[3];
    const float* b1  = (const float*)d_in[4];
    const float* w2  = (const float*)d_in[5];
    const float* b2  = (const float*)d_in[6];
    const float* w3  = (const float*)d_in[7];
    const float* b3  = (const float*)d_in[8];
    const float* wd1 = (const float*)d_in[9];
    const float* bd1 = (const float*)d_in[10];
    const float* wd2 = (const float*)d_in[11];
    float* out = (float*)d_out;

    prep_kernel<<<216, 256>>>(wd1, poses, intr);
    conv1_kernel<<<1500, 256>>>(images, w1, b1);        // 5*240*320 threads
    conv2s_kernel<<<375, 256>>>(w2, b2);                // stage 0: 96000 thr
    conv3sp_kernel<<<750, 128>>>(w3);                   // stage 1 partials
    comb3_kernel<<<750, 256>>>(b3);                     // sum + bias + relu
    build_volume_kernel<<<600, 256>>>();                // 153600
    refconv_kernel<<<dim3(38, 3), 128>>>();             // 4800 x 3 slices
    conv3d_main_kernel<<<dim3(32, 20), dim3(10, 4, 3)>>>(bd1);
    logits_kernel<<<600, 128>>>(wd2);                   // ic-split x2
    depth_out_kernel<<<19, 256>>>(out);                 // 4800
}